// round 15
// baseline (speedup 1.0000x reference)
#include <cuda_runtime.h>
#include <cuda_fp16.h>
#include <cuda_bf16.h>

#define NNODES 100000
#define NEDGES 1600000
#define INF    128
#define HF     64     // HEADS*OUT_FEATS
#define NEG_SLOPE 0.2f
#define EPS_F  1e-16f

#define NGB2 ((NNODES + 127) / 128)          // 782 gemm blocks (128 nodes each)
#define SBLK 256
#define NSB  ((NNODES + SBLK - 1) / SBLK)    // 391 scan blocks

typedef unsigned long long u64;

// ---------------- static device scratch (no allocations allowed) ----------
// State-recycling invariant: g_counts and g_state are all-zero on entry to
// every kernel_launch call (BSS-zero initially; scan re-zeroes counts after
// consuming them, scatter re-zeroes the lookback states after scan).
__device__ __half g_hh[NNODES * HF];         // 12.8 MB projected features (fp16)
__device__ float4 g_el[NNODES];              // [N][4] left scores
__device__ float4 g_er[NNODES];              // [N][4] right scores
__device__ int    g_counts[NNODES];
__device__ int    g_cursor[NNODES];
__device__ int    g_rowptr[NNODES + 1];
__device__ int    g_psrc[NEDGES];            // src ids grouped by target
__device__ u64    g_state[NSB];              // lookback: (sum<<2)|{0,1,2}
__device__ unsigned g_wt[4096];              // 16 KB: W^T fp16, pre-swizzled

// ---------------- helpers --------------------------------------------------
__device__ __forceinline__ unsigned f22u(float a, float b) {
    __half2 h = __floats2half2_rn(a, b);
    return *reinterpret_cast<unsigned*>(&h);
}

__device__ __forceinline__ void mma16816(float* c, unsigned a0, unsigned a1,
                                         unsigned a2, unsigned a3,
                                         unsigned b0, unsigned b1) {
    asm volatile(
        "mma.sync.aligned.m16n8k16.row.col.f32.f16.f16.f32 "
        "{%0,%1,%2,%3}, {%4,%5,%6,%7}, {%8,%9}, {%0,%1,%2,%3};"
        : "+f"(c[0]), "+f"(c[1]), "+f"(c[2]), "+f"(c[3])
        : "r"(a0), "r"(a1), "r"(a2), "r"(a3), "r"(b0), "r"(b1));
}

// ---------------- K0: one-shot W^T fp16 pre-swizzle -----------------------
__global__ void wprep_kernel(const float* __restrict__ W) {
    int widx = blockIdx.x * blockDim.x + threadIdx.x;
    if (widx >= 4096) return;
    int n = widx >> 6, w = widx & 63;
    int kwrd = w ^ (4 * (n & 7));
    int k0 = 2 * kwrd;
    g_wt[widx] = f22u(W[k0 * HF + n], W[(k0 + 1) * HF + n]);
}

// ---------------- K1: h = feat @ W on tensor cores (HMMA fp16 -> f32) -----
// Block: 256 threads (8 warps), 128 nodes. A tile [128][128] fp16 staged
// with XOR swizzle; W^T copied verbatim from g_wt. Fragment-direct epilogue.
__global__ __launch_bounds__(256) void gemm_kernel(
    const float* __restrict__ feat,
    const float* __restrict__ attL, const float* __restrict__ attR) {
    __shared__ uint4 smemU[3072];            // 48 KB
    unsigned* wA = reinterpret_cast<unsigned*>(smemU);        // 8192 words
    unsigned* wW = reinterpret_cast<unsigned*>(smemU + 2048); // 4096 words

    int tid = threadIdx.x;
    int base = blockIdx.x * 128;

    // --- stage A (feat -> fp16, swizzled). 2 threads per row. -------------
    {
        int row = tid >> 1, hs = tid & 1;
        int node = base + row;
        const float4* src =
            reinterpret_cast<const float4*>(feat + (size_t)node * INF + 64 * hs);
        int sw = 4 * (row & 7);
#pragma unroll
        for (int f = 0; f < 8; f++) {
            float4 v0, v1;
            if (node < NNODES) { v0 = src[2 * f]; v1 = src[2 * f + 1]; }
            else { v0 = make_float4(0,0,0,0); v1 = v0; }
            uint4 u;
            u.x = f22u(v0.x, v0.y);
            u.y = f22u(v0.z, v0.w);
            u.z = f22u(v1.x, v1.y);
            u.w = f22u(v1.z, v1.w);
            int kw = 32 * hs + 4 * f;                 // word base (mult of 4)
            *reinterpret_cast<uint4*>(&wA[row * 64 + (kw ^ sw)]) = u;
        }
    }

    // --- stage W^T: verbatim coalesced copy of pre-swizzled g_wt ----------
    {
        const uint4* src = reinterpret_cast<const uint4*>(g_wt);
        uint4* dst = reinterpret_cast<uint4*>(wW);
#pragma unroll
        for (int i = 0; i < 4; i++) dst[tid + 256 * i] = src[tid + 256 * i];
    }
    __syncthreads();

    // --- mma mainloop ------------------------------------------------------
    int lane = tid & 31, wrp = tid >> 5;
    int gid = lane >> 2, tg = lane & 3;
    int m0 = wrp * 16;
    int rA = m0 + gid, rA2 = rA + 8;
    int swA = 4 * gid;                       // (row&7)==gid for both rows

    float c[8][4];
#pragma unroll
    for (int j = 0; j < 8; j++)
#pragma unroll
        for (int q = 0; q < 4; q++) c[j][q] = 0.f;

#pragma unroll
    for (int ks = 0; ks < 8; ks++) {
        int kb = ks * 8 + tg;
        unsigned a0 = wA[rA  * 64 + (kb ^ swA)];
        unsigned a1 = wA[rA2 * 64 + (kb ^ swA)];
        unsigned a2 = wA[rA  * 64 + ((kb + 4) ^ swA)];
        unsigned a3 = wA[rA2 * 64 + ((kb + 4) ^ swA)];
#pragma unroll
        for (int j = 0; j < 8; j++) {
            int n = 8 * j + gid;             // (n&7)==gid -> same swizzle
            unsigned b0 = wW[n * 64 + (kb ^ swA)];
            unsigned b1 = wW[n * 64 + ((kb + 4) ^ swA)];
            mma16816(c[j], a0, a1, a2, a3, b0, b1);
        }
    }

    // --- fragment-direct epilogue ------------------------------------------
    int nodeA = base + rA, nodeB = base + rA2;
    bool vA = nodeA < NNODES, vB = nodeB < NNODES;
    unsigned* hword = reinterpret_cast<unsigned*>(g_hh);
    float elA[4] = {0,0,0,0}, erA[4] = {0,0,0,0};
    float elB[4] = {0,0,0,0}, erB[4] = {0,0,0,0};
#pragma unroll
    for (int j = 0; j < 8; j++) {
        int hd = j >> 1;
        float a0 = __ldg(&attL[8 * j + 2 * tg]);
        float a1 = __ldg(&attL[8 * j + 2 * tg + 1]);
        float b0 = __ldg(&attR[8 * j + 2 * tg]);
        float b1 = __ldg(&attR[8 * j + 2 * tg + 1]);
        if (vA) hword[(size_t)nodeA * 32 + 4 * j + tg] = f22u(c[j][0], c[j][1]);
        if (vB) hword[(size_t)nodeB * 32 + 4 * j + tg] = f22u(c[j][2], c[j][3]);
        elA[hd] += c[j][0] * a0 + c[j][1] * a1;
        erA[hd] += c[j][0] * b0 + c[j][1] * b1;
        elB[hd] += c[j][2] * a0 + c[j][3] * a1;
        erB[hd] += c[j][2] * b0 + c[j][3] * b1;
    }
#pragma unroll
    for (int hd = 0; hd < 4; hd++) {
        elA[hd] += __shfl_xor_sync(0xFFFFFFFFu, elA[hd], 1);
        elA[hd] += __shfl_xor_sync(0xFFFFFFFFu, elA[hd], 2);
        erA[hd] += __shfl_xor_sync(0xFFFFFFFFu, erA[hd], 1);
        erA[hd] += __shfl_xor_sync(0xFFFFFFFFu, erA[hd], 2);
        elB[hd] += __shfl_xor_sync(0xFFFFFFFFu, elB[hd], 1);
        elB[hd] += __shfl_xor_sync(0xFFFFFFFFu, elB[hd], 2);
        erB[hd] += __shfl_xor_sync(0xFFFFFFFFu, erB[hd], 1);
        erB[hd] += __shfl_xor_sync(0xFFFFFFFFu, erB[hd], 2);
    }
    if (tg == 0) {
        if (vA) {
            g_el[nodeA] = make_float4(elA[0], elA[1], elA[2], elA[3]);
            g_er[nodeA] = make_float4(erA[0], erA[1], erA[2], erA[3]);
        }
        if (vB) {
            g_el[nodeB] = make_float4(elB[0], elB[1], elB[2], elB[3]);
            g_er[nodeB] = make_float4(erB[0], erB[1], erB[2], erB[3]);
        }
    }
}

// ---------------- K2: target-degree histogram (8 edges/thread) ------------
__global__ void count_kernel(const int* __restrict__ trg) {
    int e8 = blockIdx.x * blockDim.x + threadIdx.x;
    if (e8 >= NEDGES / 8) return;
    int4 t0 = reinterpret_cast<const int4*>(trg)[e8 * 2];
    int4 t1 = reinterpret_cast<const int4*>(trg)[e8 * 2 + 1];
    atomicAdd(&g_counts[t0.x], 1);
    atomicAdd(&g_counts[t0.y], 1);
    atomicAdd(&g_counts[t0.z], 1);
    atomicAdd(&g_counts[t0.w], 1);
    atomicAdd(&g_counts[t1.x], 1);
    atomicAdd(&g_counts[t1.y], 1);
    atomicAdd(&g_counts[t1.z], 1);
    atomicAdd(&g_counts[t1.w], 1);
}

// ---------------- K3: decoupled lookback scan, warp-parallel window -------
__global__ __launch_bounds__(SBLK) void scan_kernel() {
    int b = blockIdx.x, tid = threadIdx.x;
    int lane = tid & 31, wid = tid >> 5;
    int i = b * SBLK + tid;
    int v = (i < NNODES) ? g_counts[i] : 0;

    int x = v;
#pragma unroll
    for (int off = 1; off < 32; off <<= 1) {
        int u = __shfl_up_sync(0xFFFFFFFFu, x, off);
        if (lane >= off) x += u;
    }
    __shared__ int wsum[8], woff[8];
    __shared__ int s_prev;
    if (lane == 31) wsum[wid] = x;
    __syncthreads();

    if (tid < 32) {
        int t = (lane < 8) ? wsum[lane] : 0;
        int s = t;
#pragma unroll
        for (int off = 1; off < 8; off <<= 1) {
            int u = __shfl_up_sync(0xFFFFFFFFu, s, off);
            if (lane >= off && lane < 8) s += u;
        }
        if (lane < 8) woff[lane] = s - t;
        int total = __shfl_sync(0xFFFFFFFFu, s, 7);

        if (b == 0) {
            if (lane == 0) {
                atomicExch(&g_state[0], ((u64)total << 2) | 2ull);
                s_prev = 0;
            }
        } else {
            if (lane == 0)
                atomicExch(&g_state[b], ((u64)total << 2) | 1ull);
            long long prev = 0;
            int look = b - 1;
            while (true) {
                int idx = look - lane;
                u64 st = (idx >= 0) ? atomicAdd(&g_state[idx], 0ull) : 0ull;
                u64 fl = (idx >= 0) ? (st & 3ull) : 2ull;
                unsigned ready = __ballot_sync(0xFFFFFFFFu, fl != 0ull);
                if (ready != 0xFFFFFFFFu) { __nanosleep(20); continue; }
                unsigned pmask = __ballot_sync(0xFFFFFFFFu, fl == 2ull);
                int firstP = __ffs(pmask) - 1;
                long long contrib =
                    (firstP < 0 || lane <= firstP) ? (long long)(st >> 2) : 0ll;
#pragma unroll
                for (int off = 16; off > 0; off >>= 1)
                    contrib += __shfl_down_sync(0xFFFFFFFFu, contrib, off);
                contrib = __shfl_sync(0xFFFFFFFFu, contrib, 0);
                prev += contrib;
                if (firstP >= 0) break;
                look -= 32;
            }
            if (lane == 0) {
                atomicExch(&g_state[b], ((u64)(prev + total) << 2) | 2ull);
                s_prev = (int)prev;
            }
        }
    }
    __syncthreads();
    if (i < NNODES) {
        int pos = s_prev + woff[wid] + x - v;
        g_rowptr[i] = pos;
        g_cursor[i] = pos;
        g_counts[i] = 0;                       // recycle for next call
        if (i == NNODES - 1) g_rowptr[NNODES] = NEDGES;
    }
}

// ---------------- K4: scatter src ids (8 edges/thread, high MLP) ----------
__global__ void scatter_kernel(const int* __restrict__ src,
                               const int* __restrict__ trg) {
    int e8 = blockIdx.x * blockDim.x + threadIdx.x;
    if (e8 < NSB) g_state[e8] = 0ull;          // reset for next call
    if (e8 >= NEDGES / 8) return;
    int4 t0 = reinterpret_cast<const int4*>(trg)[e8 * 2];
    int4 t1 = reinterpret_cast<const int4*>(trg)[e8 * 2 + 1];
    int4 s0 = reinterpret_cast<const int4*>(src)[e8 * 2];
    int4 s1 = reinterpret_cast<const int4*>(src)[e8 * 2 + 1];
    int p0 = atomicAdd(&g_cursor[t0.x], 1);
    int p1 = atomicAdd(&g_cursor[t0.y], 1);
    int p2 = atomicAdd(&g_cursor[t0.z], 1);
    int p3 = atomicAdd(&g_cursor[t0.w], 1);
    int p4 = atomicAdd(&g_cursor[t1.x], 1);
    int p5 = atomicAdd(&g_cursor[t1.y], 1);
    int p6 = atomicAdd(&g_cursor[t1.z], 1);
    int p7 = atomicAdd(&g_cursor[t1.w], 1);
    g_psrc[p0] = s0.x;
    g_psrc[p1] = s0.y;
    g_psrc[p2] = s0.z;
    g_psrc[p3] = s0.w;
    g_psrc[p4] = s1.x;
    g_psrc[p5] = s1.y;
    g_psrc[p6] = s1.z;
    g_psrc[p7] = s1.w;
}

// ---------------- K5: single-pass warp-per-node softmax + aggregation -----
// Unnormalized accumulate Sum(e_i * h_i); divide by Sum(e_i)+EPS at the end.
// Inner loop: 8 edges x 32B per iteration (j8 = lane>>2, head c4 = lane&2bits)
// -- each lane owns ONE full head of one edge (2 independent uint4 loads),
// halving serial iterations and doubling MLP vs the 4-edge variant.
// Combine partials across the 8 edge-groups with shfl-xor {4,8,16}.
__global__ __launch_bounds__(256) void agg_kernel(float* __restrict__ out) {
    __shared__ int   s_src[8][32];
    __shared__ float s_exp[8][32 * 4];

    int gw = (blockIdx.x * 256 + threadIdx.x) >> 5;   // node
    int lane = threadIdx.x & 31;
    int ws = (threadIdx.x >> 5);
    if (gw >= NNODES) return;

    int beg = g_rowptr[gw];
    int end = g_rowptr[gw + 1];
    float4 er = g_er[gw];
    int c4 = lane & 3;           // head index / 32B feature chunk
    int j8 = lane >> 2;          // edge sub-index within group of 8

    float acc[16];
#pragma unroll
    for (int k = 0; k < 16; k++) acc[k] = 0.f;
    float4 dp = make_float4(0.f, 0.f, 0.f, 0.f);   // per-lane denom partials
    const char* hb = reinterpret_cast<const char*>(g_hh);

    for (int t0 = beg; t0 < end; t0 += 32) {
        int cnt = min(32, end - t0);
        int s = 0;
        float4 e4 = make_float4(0.f, 0.f, 0.f, 0.f);
        if (lane < cnt) {
            s = __ldg(&g_psrc[t0 + lane]);          // sequential coalesced
            float4 l = g_el[s];                     // 16B gather, L2-resident
            float sx = l.x + er.x, sy = l.y + er.y;
            float sz = l.z + er.z, sw = l.w + er.w;
            sx = sx > 0.f ? sx : NEG_SLOPE * sx;
            sy = sy > 0.f ? sy : NEG_SLOPE * sy;
            sz = sz > 0.f ? sz : NEG_SLOPE * sz;
            sw = sw > 0.f ? sw : NEG_SLOPE * sw;
            e4 = make_float4(__expf(sx), __expf(sy), __expf(sz), __expf(sw));
            dp.x += e4.x; dp.y += e4.y; dp.z += e4.z; dp.w += e4.w;
        }
        s_src[ws][lane] = s;                        // inactive lanes: 0, a=0
        reinterpret_cast<float4*>(s_exp[ws])[lane] = e4;
        __syncwarp();

        int nIter = (cnt + 7) >> 3;
#pragma unroll 2
        for (int g = 0; g < nIter; g++) {
            int j = g * 8 + j8;                     // j <= 31 always
            int sj = s_src[ws][j];
            float a = s_exp[ws][j * 4 + c4];
            const uint4* hp = reinterpret_cast<const uint4*>(
                hb + (size_t)sj * 128 + c4 * 32);
            uint4 h0 = hp[0];                       // 2 independent 16B loads
            uint4 h1 = hp[1];
            float2 f;
            f = __half22float2(*reinterpret_cast<__half2*>(&h0.x));
            acc[0] = fmaf(f.x, a, acc[0]);  acc[1] = fmaf(f.y, a, acc[1]);
            f = __half22float2(*reinterpret_cast<__half2*>(&h0.y));
            acc[2] = fmaf(f.x, a, acc[2]);  acc[3] = fmaf(f.y, a, acc[3]);
            f = __half22float2(*reinterpret_cast<__half2*>(&h0.z));
            acc[4] = fmaf(f.x, a, acc[4]);  acc[5] = fmaf(f.y, a, acc[5]);
            f = __half22float2(*reinterpret_cast<__half2*>(&h0.w));
            acc[6] = fmaf(f.x, a, acc[6]);  acc[7] = fmaf(f.y, a, acc[7]);
            f = __half22float2(*reinterpret_cast<__half2*>(&h1.x));
            acc[8] = fmaf(f.x, a, acc[8]);  acc[9] = fmaf(f.y, a, acc[9]);
            f = __half22float2(*reinterpret_cast<__half2*>(&h1.y));
            acc[10] = fmaf(f.x, a, acc[10]); acc[11] = fmaf(f.y, a, acc[11]);
            f = __half22float2(*reinterpret_cast<__half2*>(&h1.z));
            acc[12] = fmaf(f.x, a, acc[12]); acc[13] = fmaf(f.y, a, acc[13]);
            f = __half22float2(*reinterpret_cast<__half2*>(&h1.w));
            acc[14] = fmaf(f.x, a, acc[14]); acc[15] = fmaf(f.y, a, acc[15]);
        }
        __syncwarp();
    }

    // combine partial sums across the 8 j8 groups (lanes xor 4, 8, 16)
#pragma unroll
    for (int k = 0; k < 16; k++) {
        acc[k] += __shfl_xor_sync(0xFFFFFFFFu, acc[k], 4);
        acc[k] += __shfl_xor_sync(0xFFFFFFFFu, acc[k], 8);
        acc[k] += __shfl_xor_sync(0xFFFFFFFFu, acc[k], 16);
    }

    // reduce denom partials across all lanes
#pragma unroll
    for (int off = 16; off > 0; off >>= 1) {
        dp.x += __shfl_xor_sync(0xFFFFFFFFu, dp.x, off);
        dp.y += __shfl_xor_sync(0xFFFFFFFFu, dp.y, off);
        dp.z += __shfl_xor_sync(0xFFFFFFFFu, dp.z, off);
        dp.w += __shfl_xor_sync(0xFFFFFFFFu, dp.w, off);
    }
    float denom = (c4 == 0) ? dp.x : (c4 == 1) ? dp.y
                : (c4 == 2) ? dp.z : dp.w;
    float rd = 1.0f / (denom + EPS_F);

    if (j8 == 0) {                                 // lanes 0..3 write the row
        float4* orow = reinterpret_cast<float4*>(out + (size_t)gw * HF + c4 * 16);
        orow[0] = make_float4(acc[0] * rd, acc[1] * rd, acc[2] * rd, acc[3] * rd);
        orow[1] = make_float4(acc[4] * rd, acc[5] * rd, acc[6] * rd, acc[7] * rd);
        orow[2] = make_float4(acc[8] * rd, acc[9] * rd, acc[10] * rd, acc[11] * rd);
        orow[3] = make_float4(acc[12] * rd, acc[13] * rd, acc[14] * rd, acc[15] * rd);
    }
}

// ---------------- launch ---------------------------------------------------
// Fork kept (worth ~6-10us, R13/R14). Submission order puts scatter in ncu's
// 4th slot this round (graph topology unchanged: gemm depends only on wprep
// via stream s2, so it still overlaps the CSR build).
extern "C" void kernel_launch(void* const* d_in, const int* in_sizes, int n_in,
                              void* d_out, int out_size) {
    const float* feat = (const float*)d_in[0];
    const float* W    = (const float*)d_in[1];
    const float* attL = (const float*)d_in[2];
    const float* attR = (const float*)d_in[3];
    const int*   src  = (const int*)d_in[4];
    const int*   trg  = (const int*)d_in[5];
    float* out = (float*)d_out;

    static cudaStream_t s2 = 0;
    static cudaEvent_t  e0 = 0, e1 = 0;
    static bool ready = false;
    if (!ready) {
        bool ok = (cudaStreamCreateWithFlags(&s2, cudaStreamNonBlocking) == cudaSuccess)
               && (cudaEventCreateWithFlags(&e0, cudaEventDisableTiming) == cudaSuccess)
               && (cudaEventCreateWithFlags(&e1, cudaEventDisableTiming) == cudaSuccess);
        if (!ok) { s2 = 0; e0 = e1 = 0; }
        ready = true;
    }

    bool fork = (s2 != 0);
    if (fork) {
        cudaEventRecord(e0, 0);
        cudaStreamWaitEvent(s2, e0, 0);
    }
    cudaStream_t sg = fork ? s2 : 0;

    wprep_kernel<<<16, 256, 0, sg>>>(W);                         // slot 1
    count_kernel<<<(NEDGES / 8 + 255) / 256, 256>>>(trg);        // slot 2
    scan_kernel<<<NSB, SBLK>>>();                                // slot 3
    scatter_kernel<<<(NEDGES / 8 + 255) / 256, 256>>>(src, trg); // slot 4 (ncu)
    gemm_kernel<<<NGB2, 256, 0, sg>>>(feat, attL, attR);         // slot 5
    if (fork) cudaEventRecord(e1, s2);

    if (fork) cudaStreamWaitEvent(0, e1, 0);
    agg_kernel<<<(NNODES * 32 + 255) / 256, 256>>>(out);         // slot 6
}

// round 17
// speedup vs baseline: 1.0814x; 1.0814x over previous
#include <cuda_runtime.h>
#include <cuda_fp16.h>
#include <cuda_bf16.h>

#define NNODES 100000
#define NEDGES 1600000
#define INF    128
#define HF     64     // HEADS*OUT_FEATS
#define NEG_SLOPE 0.2f
#define EPS_F  1e-16f

#define NGB2 ((NNODES + 127) / 128)          // 782 gemm blocks (128 nodes each)
#define SBLK 256
#define NSB  ((NNODES + SBLK - 1) / SBLK)    // 391 scan blocks

typedef unsigned long long u64;

// ---------------- static device scratch (no allocations allowed) ----------
// State-recycling invariant: g_counts and g_state are all-zero on entry to
// every kernel_launch call (BSS-zero initially; scan re-zeroes counts after
// consuming them, scatter re-zeroes the lookback states after scan).
__device__ __half g_hh[NNODES * HF];         // 12.8 MB projected features (fp16)
__device__ float4 g_el[NNODES];              // [N][4] left scores
__device__ float4 g_er[NNODES];              // [N][4] right scores
__device__ int    g_counts[NNODES];
__device__ int    g_rowptr[NNODES + 1];
__device__ int    g_rank[NEDGES];            // per-edge rank within target
__device__ int    g_psrc[NEDGES];            // src ids grouped by target
__device__ u64    g_state[NSB];              // lookback: (sum<<2)|{0,1,2}
__device__ unsigned g_wt[4096];              // 16 KB: W^T fp16, pre-swizzled

// ---------------- helpers --------------------------------------------------
__device__ __forceinline__ unsigned f22u(float a, float b) {
    __half2 h = __floats2half2_rn(a, b);
    return *reinterpret_cast<unsigned*>(&h);
}

__device__ __forceinline__ void mma16816(float* c, unsigned a0, unsigned a1,
                                         unsigned a2, unsigned a3,
                                         unsigned b0, unsigned b1) {
    asm volatile(
        "mma.sync.aligned.m16n8k16.row.col.f32.f16.f16.f32 "
        "{%0,%1,%2,%3}, {%4,%5,%6,%7}, {%8,%9}, {%0,%1,%2,%3};"
        : "+f"(c[0]), "+f"(c[1]), "+f"(c[2]), "+f"(c[3])
        : "r"(a0), "r"(a1), "r"(a2), "r"(a3), "r"(b0), "r"(b1));
}

// ---------------- K0: one-shot W^T fp16 pre-swizzle -----------------------
__global__ void wprep_kernel(const float* __restrict__ W) {
    int widx = blockIdx.x * blockDim.x + threadIdx.x;
    if (widx >= 4096) return;
    int n = widx >> 6, w = widx & 63;
    int kwrd = w ^ (4 * (n & 7));
    int k0 = 2 * kwrd;
    g_wt[widx] = f22u(W[k0 * HF + n], W[(k0 + 1) * HF + n]);
}

// ---------------- K1: h = feat @ W on tensor cores (HMMA fp16 -> f32) -----
// Block: 256 threads (8 warps), 128 nodes. A tile [128][128] fp16 staged
// with XOR swizzle; W^T copied verbatim from g_wt. Fragment-direct epilogue.
__global__ __launch_bounds__(256) void gemm_kernel(
    const float* __restrict__ feat,
    const float* __restrict__ attL, const float* __restrict__ attR) {
    __shared__ uint4 smemU[3072];            // 48 KB
    unsigned* wA = reinterpret_cast<unsigned*>(smemU);        // 8192 words
    unsigned* wW = reinterpret_cast<unsigned*>(smemU + 2048); // 4096 words

    int tid = threadIdx.x;
    int base = blockIdx.x * 128;

    // --- stage A (feat -> fp16, swizzled). 2 threads per row. -------------
    {
        int row = tid >> 1, hs = tid & 1;
        int node = base + row;
        const float4* src =
            reinterpret_cast<const float4*>(feat + (size_t)node * INF + 64 * hs);
        int sw = 4 * (row & 7);
#pragma unroll
        for (int f = 0; f < 8; f++) {
            float4 v0, v1;
            if (node < NNODES) { v0 = src[2 * f]; v1 = src[2 * f + 1]; }
            else { v0 = make_float4(0,0,0,0); v1 = v0; }
            uint4 u;
            u.x = f22u(v0.x, v0.y);
            u.y = f22u(v0.z, v0.w);
            u.z = f22u(v1.x, v1.y);
            u.w = f22u(v1.z, v1.w);
            int kw = 32 * hs + 4 * f;                 // word base (mult of 4)
            *reinterpret_cast<uint4*>(&wA[row * 64 + (kw ^ sw)]) = u;
        }
    }

    // --- stage W^T: verbatim coalesced copy of pre-swizzled g_wt ----------
    {
        const uint4* src = reinterpret_cast<const uint4*>(g_wt);
        uint4* dst = reinterpret_cast<uint4*>(wW);
#pragma unroll
        for (int i = 0; i < 4; i++) dst[tid + 256 * i] = src[tid + 256 * i];
    }
    __syncthreads();

    // --- mma mainloop ------------------------------------------------------
    int lane = tid & 31, wrp = tid >> 5;
    int gid = lane >> 2, tg = lane & 3;
    int m0 = wrp * 16;
    int rA = m0 + gid, rA2 = rA + 8;
    int swA = 4 * gid;                       // (row&7)==gid for both rows

    float c[8][4];
#pragma unroll
    for (int j = 0; j < 8; j++)
#pragma unroll
        for (int q = 0; q < 4; q++) c[j][q] = 0.f;

#pragma unroll
    for (int ks = 0; ks < 8; ks++) {
        int kb = ks * 8 + tg;
        unsigned a0 = wA[rA  * 64 + (kb ^ swA)];
        unsigned a1 = wA[rA2 * 64 + (kb ^ swA)];
        unsigned a2 = wA[rA  * 64 + ((kb + 4) ^ swA)];
        unsigned a3 = wA[rA2 * 64 + ((kb + 4) ^ swA)];
#pragma unroll
        for (int j = 0; j < 8; j++) {
            int n = 8 * j + gid;             // (n&7)==gid -> same swizzle
            unsigned b0 = wW[n * 64 + (kb ^ swA)];
            unsigned b1 = wW[n * 64 + ((kb + 4) ^ swA)];
            mma16816(c[j], a0, a1, a2, a3, b0, b1);
        }
    }

    // --- fragment-direct epilogue ------------------------------------------
    int nodeA = base + rA, nodeB = base + rA2;
    bool vA = nodeA < NNODES, vB = nodeB < NNODES;
    unsigned* hword = reinterpret_cast<unsigned*>(g_hh);
    float elA[4] = {0,0,0,0}, erA[4] = {0,0,0,0};
    float elB[4] = {0,0,0,0}, erB[4] = {0,0,0,0};
#pragma unroll
    for (int j = 0; j < 8; j++) {
        int hd = j >> 1;
        float a0 = __ldg(&attL[8 * j + 2 * tg]);
        float a1 = __ldg(&attL[8 * j + 2 * tg + 1]);
        float b0 = __ldg(&attR[8 * j + 2 * tg]);
        float b1 = __ldg(&attR[8 * j + 2 * tg + 1]);
        if (vA) hword[(size_t)nodeA * 32 + 4 * j + tg] = f22u(c[j][0], c[j][1]);
        if (vB) hword[(size_t)nodeB * 32 + 4 * j + tg] = f22u(c[j][2], c[j][3]);
        elA[hd] += c[j][0] * a0 + c[j][1] * a1;
        erA[hd] += c[j][0] * b0 + c[j][1] * b1;
        elB[hd] += c[j][2] * a0 + c[j][3] * a1;
        erB[hd] += c[j][2] * b0 + c[j][3] * b1;
    }
#pragma unroll
    for (int hd = 0; hd < 4; hd++) {
        elA[hd] += __shfl_xor_sync(0xFFFFFFFFu, elA[hd], 1);
        elA[hd] += __shfl_xor_sync(0xFFFFFFFFu, elA[hd], 2);
        erA[hd] += __shfl_xor_sync(0xFFFFFFFFu, erA[hd], 1);
        erA[hd] += __shfl_xor_sync(0xFFFFFFFFu, erA[hd], 2);
        elB[hd] += __shfl_xor_sync(0xFFFFFFFFu, elB[hd], 1);
        elB[hd] += __shfl_xor_sync(0xFFFFFFFFu, elB[hd], 2);
        erB[hd] += __shfl_xor_sync(0xFFFFFFFFu, erB[hd], 1);
        erB[hd] += __shfl_xor_sync(0xFFFFFFFFu, erB[hd], 2);
    }
    if (tg == 0) {
        if (vA) {
            g_el[nodeA] = make_float4(elA[0], elA[1], elA[2], elA[3]);
            g_er[nodeA] = make_float4(erA[0], erA[1], erA[2], erA[3]);
        }
        if (vB) {
            g_el[nodeB] = make_float4(elB[0], elB[1], elB[2], elB[3]);
            g_er[nodeB] = make_float4(erB[0], erB[1], erB[2], erB[3]);
        }
    }
}

// ---------------- K2: degree histogram + per-edge rank --------------------
// Stores the atomicAdd return value (the edge's rank within its target) so
// scatter needs no atomics at all.
__global__ void count_kernel(const int* __restrict__ trg) {
    int e8 = blockIdx.x * blockDim.x + threadIdx.x;
    if (e8 >= NEDGES / 8) return;
    int4 t0 = reinterpret_cast<const int4*>(trg)[e8 * 2];
    int4 t1 = reinterpret_cast<const int4*>(trg)[e8 * 2 + 1];
    int4 r0, r1;
    r0.x = atomicAdd(&g_counts[t0.x], 1);
    r0.y = atomicAdd(&g_counts[t0.y], 1);
    r0.z = atomicAdd(&g_counts[t0.z], 1);
    r0.w = atomicAdd(&g_counts[t0.w], 1);
    r1.x = atomicAdd(&g_counts[t1.x], 1);
    r1.y = atomicAdd(&g_counts[t1.y], 1);
    r1.z = atomicAdd(&g_counts[t1.z], 1);
    r1.w = atomicAdd(&g_counts[t1.w], 1);
    reinterpret_cast<int4*>(g_rank)[e8 * 2]     = r0;   // coalesced
    reinterpret_cast<int4*>(g_rank)[e8 * 2 + 1] = r1;
}

// ---------------- K3: decoupled lookback scan, warp-parallel window -------
__global__ __launch_bounds__(SBLK) void scan_kernel() {
    int b = blockIdx.x, tid = threadIdx.x;
    int lane = tid & 31, wid = tid >> 5;
    int i = b * SBLK + tid;
    int v = (i < NNODES) ? g_counts[i] : 0;

    int x = v;
#pragma unroll
    for (int off = 1; off < 32; off <<= 1) {
        int u = __shfl_up_sync(0xFFFFFFFFu, x, off);
        if (lane >= off) x += u;
    }
    __shared__ int wsum[8], woff[8];
    __shared__ int s_prev;
    if (lane == 31) wsum[wid] = x;
    __syncthreads();

    if (tid < 32) {
        int t = (lane < 8) ? wsum[lane] : 0;
        int s = t;
#pragma unroll
        for (int off = 1; off < 8; off <<= 1) {
            int u = __shfl_up_sync(0xFFFFFFFFu, s, off);
            if (lane >= off && lane < 8) s += u;
        }
        if (lane < 8) woff[lane] = s - t;
        int total = __shfl_sync(0xFFFFFFFFu, s, 7);

        if (b == 0) {
            if (lane == 0) {
                atomicExch(&g_state[0], ((u64)total << 2) | 2ull);
                s_prev = 0;
            }
        } else {
            if (lane == 0)
                atomicExch(&g_state[b], ((u64)total << 2) | 1ull);
            long long prev = 0;
            int look = b - 1;
            while (true) {
                int idx = look - lane;
                u64 st = (idx >= 0) ? atomicAdd(&g_state[idx], 0ull) : 0ull;
                u64 fl = (idx >= 0) ? (st & 3ull) : 2ull;
                unsigned ready = __ballot_sync(0xFFFFFFFFu, fl != 0ull);
                if (ready != 0xFFFFFFFFu) { __nanosleep(20); continue; }
                unsigned pmask = __ballot_sync(0xFFFFFFFFu, fl == 2ull);
                int firstP = __ffs(pmask) - 1;
                long long contrib =
                    (firstP < 0 || lane <= firstP) ? (long long)(st >> 2) : 0ll;
#pragma unroll
                for (int off = 16; off > 0; off >>= 1)
                    contrib += __shfl_down_sync(0xFFFFFFFFu, contrib, off);
                contrib = __shfl_sync(0xFFFFFFFFu, contrib, 0);
                prev += contrib;
                if (firstP >= 0) break;
                look -= 32;
            }
            if (lane == 0) {
                atomicExch(&g_state[b], ((u64)(prev + total) << 2) | 2ull);
                s_prev = (int)prev;
            }
        }
    }
    __syncthreads();
    if (i < NNODES) {
        g_rowptr[i] = s_prev + woff[wid] + x - v;  // global exclusive prefix
        g_counts[i] = 0;                           // recycle for next call
        if (i == NNODES - 1) g_rowptr[NNODES] = NEDGES;
    }
}

// ---------------- K4: atomic-free scatter (8 edges/thread) ----------------
// pos = rowptr[t] + rank[e]; pure loads + scattered stores, MLP=8.
// Also recycles lookback state for the next call.
__global__ void scatter_kernel(const int* __restrict__ src,
                               const int* __restrict__ trg) {
    int e8 = blockIdx.x * blockDim.x + threadIdx.x;
    if (e8 < NSB) g_state[e8] = 0ull;          // reset for next call
    if (e8 >= NEDGES / 8) return;
    int4 t0 = reinterpret_cast<const int4*>(trg)[e8 * 2];
    int4 t1 = reinterpret_cast<const int4*>(trg)[e8 * 2 + 1];
    int4 s0 = reinterpret_cast<const int4*>(src)[e8 * 2];
    int4 s1 = reinterpret_cast<const int4*>(src)[e8 * 2 + 1];
    int4 r0 = reinterpret_cast<const int4*>(g_rank)[e8 * 2];
    int4 r1 = reinterpret_cast<const int4*>(g_rank)[e8 * 2 + 1];
    int p0 = __ldg(&g_rowptr[t0.x]) + r0.x;
    int p1 = __ldg(&g_rowptr[t0.y]) + r0.y;
    int p2 = __ldg(&g_rowptr[t0.z]) + r0.z;
    int p3 = __ldg(&g_rowptr[t0.w]) + r0.w;
    int p4 = __ldg(&g_rowptr[t1.x]) + r1.x;
    int p5 = __ldg(&g_rowptr[t1.y]) + r1.y;
    int p6 = __ldg(&g_rowptr[t1.z]) + r1.z;
    int p7 = __ldg(&g_rowptr[t1.w]) + r1.w;
    g_psrc[p0] = s0.x;
    g_psrc[p1] = s0.y;
    g_psrc[p2] = s0.z;
    g_psrc[p3] = s0.w;
    g_psrc[p4] = s1.x;
    g_psrc[p5] = s1.y;
    g_psrc[p6] = s1.z;
    g_psrc[p7] = s1.w;
}

// ---------------- K5: single-pass warp-per-node softmax + aggregation -----
// Unnormalized accumulate Sum(e_i * h_i); divide by Sum(e_i)+EPS at the end.
// Inner loop: 4 edges x 16B per iteration (jsub = lane>>3, chunk c = lane&7),
// then combine partials across jsub groups with shfl-xor. (R14 variant —
// the 8-edge restructure regressed and was reverted.)
__global__ __launch_bounds__(256) void agg_kernel(float* __restrict__ out) {
    __shared__ int   s_src[8][32];
    __shared__ float s_exp[8][32 * 4];

    int gw = (blockIdx.x * 256 + threadIdx.x) >> 5;   // node
    int lane = threadIdx.x & 31;
    int ws = (threadIdx.x >> 5);
    if (gw >= NNODES) return;

    int beg = g_rowptr[gw];
    int end = g_rowptr[gw + 1];
    float4 er = g_er[gw];
    int c = lane & 7;            // feature chunk: halfs [8c, 8c+8)
    int jsub = lane >> 3;        // edge sub-index within group of 4
    int head = c >> 1;           // head of this feature chunk

    float acc[8];
#pragma unroll
    for (int k = 0; k < 8; k++) acc[k] = 0.f;
    float4 dp = make_float4(0.f, 0.f, 0.f, 0.f);   // per-lane denom partials
    const char* hb = reinterpret_cast<const char*>(g_hh);

    for (int t0 = beg; t0 < end; t0 += 32) {
        int cnt = min(32, end - t0);
        int s = 0;
        float4 e4 = make_float4(0.f, 0.f, 0.f, 0.f);
        if (lane < cnt) {
            s = __ldg(&g_psrc[t0 + lane]);          // sequential coalesced
            float4 l = g_el[s];                     // 16B gather, L2-resident
            float sx = l.x + er.x, sy = l.y + er.y;
            float sz = l.z + er.z, sw = l.w + er.w;
            sx = sx > 0.f ? sx : NEG_SLOPE * sx;
            sy = sy > 0.f ? sy : NEG_SLOPE * sy;
            sz = sz > 0.f ? sz : NEG_SLOPE * sz;
            sw = sw > 0.f ? sw : NEG_SLOPE * sw;
            e4 = make_float4(__expf(sx), __expf(sy), __expf(sz), __expf(sw));
            dp.x += e4.x; dp.y += e4.y; dp.z += e4.z; dp.w += e4.w;
        }
        s_src[ws][lane] = s;                        // inactive lanes: 0, a=0
        reinterpret_cast<float4*>(s_exp[ws])[lane] = e4;
        __syncwarp();

        int nIter = (cnt + 3) >> 2;
#pragma unroll 2
        for (int j4 = 0; j4 < nIter; j4++) {
            int j = j4 * 4 + jsub;                  // j <= 31 always
            int sj = s_src[ws][j];
            float a = s_exp[ws][j * 4 + head];
            uint4 hv = *reinterpret_cast<const uint4*>(
                hb + (size_t)sj * 128 + c * 16);
            float2 f0 = __half22float2(*reinterpret_cast<__half2*>(&hv.x));
            float2 f1 = __half22float2(*reinterpret_cast<__half2*>(&hv.y));
            float2 f2 = __half22float2(*reinterpret_cast<__half2*>(&hv.z));
            float2 f3 = __half22float2(*reinterpret_cast<__half2*>(&hv.w));
            acc[0] = fmaf(f0.x, a, acc[0]);
            acc[1] = fmaf(f0.y, a, acc[1]);
            acc[2] = fmaf(f1.x, a, acc[2]);
            acc[3] = fmaf(f1.y, a, acc[3]);
            acc[4] = fmaf(f2.x, a, acc[4]);
            acc[5] = fmaf(f2.y, a, acc[5]);
            acc[6] = fmaf(f3.x, a, acc[6]);
            acc[7] = fmaf(f3.y, a, acc[7]);
        }
        __syncwarp();
    }

    // combine partial sums across the 4 jsub groups (lanes xor 8, 16)
#pragma unroll
    for (int k = 0; k < 8; k++) {
        acc[k] += __shfl_xor_sync(0xFFFFFFFFu, acc[k], 8);
        acc[k] += __shfl_xor_sync(0xFFFFFFFFu, acc[k], 16);
    }

    // reduce denom partials across all lanes
#pragma unroll
    for (int off = 16; off > 0; off >>= 1) {
        dp.x += __shfl_xor_sync(0xFFFFFFFFu, dp.x, off);
        dp.y += __shfl_xor_sync(0xFFFFFFFFu, dp.y, off);
        dp.z += __shfl_xor_sync(0xFFFFFFFFu, dp.z, off);
        dp.w += __shfl_xor_sync(0xFFFFFFFFu, dp.w, off);
    }
    float denom = (head == 0) ? dp.x : (head == 1) ? dp.y
                : (head == 2) ? dp.z : dp.w;
    float rd = 1.0f / (denom + EPS_F);

    if (jsub == 0) {                               // lanes 0..7 write the row
        float4* orow = reinterpret_cast<float4*>(out + (size_t)gw * HF + c * 8);
        orow[0] = make_float4(acc[0] * rd, acc[1] * rd, acc[2] * rd, acc[3] * rd);
        orow[1] = make_float4(acc[4] * rd, acc[5] * rd, acc[6] * rd, acc[7] * rd);
    }
}

// ---------------- launch ---------------------------------------------------
// Fork kept (worth ~6-10us). scatter stays in ncu's 4th slot to verify the
// atomic-free rewrite; gemm (slot 5, s2) still overlaps the CSR build.
extern "C" void kernel_launch(void* const* d_in, const int* in_sizes, int n_in,
                              void* d_out, int out_size) {
    const float* feat = (const float*)d_in[0];
    const float* W    = (const float*)d_in[1];
    const float* attL = (const float*)d_in[2];
    const float* attR = (const float*)d_in[3];
    const int*   src  = (const int*)d_in[4];
    const int*   trg  = (const int*)d_in[5];
    float* out = (float*)d_out;

    static cudaStream_t s2 = 0;
    static cudaEvent_t  e0 = 0, e1 = 0;
    static bool ready = false;
    if (!ready) {
        bool ok = (cudaStreamCreateWithFlags(&s2, cudaStreamNonBlocking) == cudaSuccess)
               && (cudaEventCreateWithFlags(&e0, cudaEventDisableTiming) == cudaSuccess)
               && (cudaEventCreateWithFlags(&e1, cudaEventDisableTiming) == cudaSuccess);
        if (!ok) { s2 = 0; e0 = e1 = 0; }
        ready = true;
    }

    bool fork = (s2 != 0);
    if (fork) {
        cudaEventRecord(e0, 0);
        cudaStreamWaitEvent(s2, e0, 0);
    }
    cudaStream_t sg = fork ? s2 : 0;

    wprep_kernel<<<16, 256, 0, sg>>>(W);                         // slot 1
    count_kernel<<<(NEDGES / 8 + 255) / 256, 256>>>(trg);        // slot 2
    scan_kernel<<<NSB, SBLK>>>();                                // slot 3
    scatter_kernel<<<(NEDGES / 8 + 255) / 256, 256>>>(src, trg); // slot 4 (ncu)
    gemm_kernel<<<NGB2, 256, 0, sg>>>(feat, attL, attR);         // slot 5
    if (fork) cudaEventRecord(e1, s2);

    if (fork) cudaStreamWaitEvent(0, e1, 0);
    agg_kernel<<<(NNODES * 32 + 255) / 256, 256>>>(out);         // slot 6
}